// round 16
// baseline (speedup 1.0000x reference)
#include <cuda_runtime.h>
#include <cuda_fp16.h>
#include <cstdint>

#define NMAX 100000
#define EMAX 1600000
#define SCAN_T 1024
#define MAXBLK 128

// ---------------- scratch (device globals, device-side references only) -----
// g_cnt / g_deg are zero/1.0f-initialized at module load and RE-ESTABLISHED by
// k_scan3 at the end of every launch, so no init kernel is needed.
__device__ float  g_deg  [NMAX];      // reset to 1.0f by k_scan3 (self-loop w)
__device__ float  g_dinv [NMAX];
__device__ int    g_cnt  [NMAX];      // reset to 0 by k_scan3
__device__ int    g_part [NMAX];
__device__ int    g_bsum [MAXBLK];
__device__ int    g_ptr  [NMAX + 1];
__device__ int    g_cur  [NMAX];
__device__ int2   g_edge [EMAX];       // CSR slot: (src row, norm bits)
__device__ __half2 g_xw1h[NMAX * 32];  // fp16 gather table, layer 1 (64 feat)
__device__ __half2 g_h1h [NMAX * 32];  // fp16 tanh(agg1) (streamed)
__device__ __half g_xw2h[NMAX * 32];   // fp16 gather table, layer 2
__device__ __half g_xw3h[NMAX * 16];   // fp16 gather table, layer 3

// module-load defaults: g_deg must start at 1.0f on the very first call
__device__ float g_deg_init_guard;     // (unused; g_deg handled below)

// NOTE: zero-init gives g_deg = 0.0f at load, but the FIRST k_cnt call
// accumulates on top of the initial value. To keep first-call correctness
// without an init kernel, k_scan3 computes deg = 1.0f + raw_sum where raw_sum
// comes from g_deg accumulated from 0 — so g_deg holds ONLY the edge-weight
// sum (reset to 0.0f, not 1.0f).

// ---------------- int32/int64 probe (per-thread, broadcast-coalesced) -------
__device__ __forceinline__ int probe_is64(const int* ei) {
    int z = 0;
#pragma unroll
    for (int j = 1; j < 16; j += 2) z |= ei[j];
    return (z == 0) ? 1 : 0;
}

__device__ __forceinline__ int load_idx(const int* ei, int pos, int is64) {
    return is64 ? ei[2 * pos] : ei[pos];
}

// count + degree accumulation in one pass (g_cnt/g_deg start at 0)
__global__ void k_cnt(const int* __restrict__ ei, const float* __restrict__ ew,
                      int E, int N) {
    int is64 = probe_is64(ei);
    int e = blockIdx.x * blockDim.x + threadIdx.x;
    if (e < E) {
        int c = load_idx(ei, E + e, is64);
        if ((unsigned)c >= (unsigned)N) c = 0;
        atomicAdd(&g_cnt[c], 1);
        atomicAdd(&g_deg[c], ew[e]);
    }
}

// ---------------- 3-phase parallel exclusive scan of g_cnt ------------------
__global__ void k_scan1(int n) {
    __shared__ int swarp[32];
    int i = blockIdx.x * SCAN_T + threadIdx.x;
    int lane = threadIdx.x & 31;
    int warp = threadIdx.x >> 5;
    int v = (i < n) ? g_cnt[i] : 0;
    int x = v;
#pragma unroll
    for (int o = 1; o < 32; o <<= 1) {
        int y = __shfl_up_sync(0xffffffffu, x, o);
        if (lane >= o) x += y;
    }
    if (lane == 31) swarp[warp] = x;
    __syncthreads();
    if (warp == 0) {
        int w = swarp[lane];
#pragma unroll
        for (int o = 1; o < 32; o <<= 1) {
            int y = __shfl_up_sync(0xffffffffu, w, o);
            if (lane >= o) w += y;
        }
        swarp[lane] = w;
    }
    __syncthreads();
    int warpoff = (warp > 0) ? swarp[warp - 1] : 0;
    if (i < n) g_part[i] = warpoff + x - v;
    if (threadIdx.x == SCAN_T - 1) g_bsum[blockIdx.x] = warpoff + x;
}

__global__ void k_scan2(int nb) {
    __shared__ int s[128];
    int t = threadIdx.x;
    int v = (t < nb) ? g_bsum[t] : 0;
    s[t] = v;
    __syncthreads();
#pragma unroll
    for (int o = 1; o < 128; o <<= 1) {
        int y = (t >= o) ? s[t - o] : 0;
        __syncthreads();
        s[t] += y;
        __syncthreads();
    }
    if (t < nb) g_bsum[t] = s[t] - v;
}

// phase 3: emit ptr/cur, dinv = rsqrt(1 + degsum); RESET g_cnt/g_deg for the
// next replay (deterministic: every launch sees the same initial state)
__global__ void k_scan3(int n, int E) {
    int i = blockIdx.x * SCAN_T + threadIdx.x;
    if (i < n) {
        int p = g_part[i] + g_bsum[blockIdx.x];
        g_ptr[i] = p;
        g_cur[i] = p;
        g_dinv[i] = rsqrtf(1.0f + g_deg[i]);
        g_cnt[i] = 0;
        g_deg[i] = 0.0f;
    }
    if (i == 0) g_ptr[n] = E;
}

// fill CSR slots with (src row, FINAL symmetric norm)
__global__ void k_fill(const int* __restrict__ ei, const float* __restrict__ ew,
                       int E, int N) {
    int is64 = probe_is64(ei);
    int e = blockIdx.x * blockDim.x + threadIdx.x;
    if (e >= E) return;
    int r = load_idx(ei, e, is64);
    int c = load_idx(ei, E + e, is64);
    if ((unsigned)r >= (unsigned)N) r = 0;
    if ((unsigned)c >= (unsigned)N) c = 0;
    float nm = g_dinv[r] * ew[e] * g_dinv[c];
    int pos = atomicAdd(&g_cur[c], 1);
    g_edge[pos] = make_int2(r, __float_as_int(nm));
}

// ---------------- SIMT GEMM: BM=128, 8 x TN tile, fp32 math, fp16 output ----
// IT = input element type (float or __half)
template<int K, int FOUT, int TN, bool TANH, typename IT>
__device__ __forceinline__ void gemm_body(const IT* __restrict__ X,
                                          const float* __restrict__ W,
                                          __half* __restrict__ out, int N) {
    constexpr int BM = 128;
    constexpr int TM = 8;
    constexpr int KC = 32;
    __shared__ float sW[K * FOUT];
    __shared__ float sXT[KC][BM + 1];

    const int tid = threadIdx.x;
    const int tx  = tid & 15;
    const int ty  = tid >> 4;
    const int row0 = blockIdx.x * BM;

    {
        const float4* W4 = reinterpret_cast<const float4*>(W);
        float4* sW4 = reinterpret_cast<float4*>(sW);
        for (int i = tid; i < K * FOUT / 4; i += 256) sW4[i] = W4[i];
    }

    float acc[TM][TN];
#pragma unroll
    for (int i = 0; i < TM; i++)
#pragma unroll
        for (int j = 0; j < TN; j++) acc[i][j] = 0.0f;

    for (int k0 = 0; k0 < K; k0 += KC) {
        __syncthreads();
#pragma unroll
        for (int t = 0; t < (BM * KC / 4) / 256; t++) {
            int v = tid + 256 * t;
            int row = v >> 3;
            int cp  = v & 7;
            int gr = row0 + row;
            float4 val = make_float4(0.f, 0.f, 0.f, 0.f);
            if (gr < N) {
                if constexpr (sizeof(IT) == 2) {
                    const __half2* src = reinterpret_cast<const __half2*>(
                        X + (size_t)gr * K + k0 + cp * 4);
                    float2 f01 = __half22float2(src[0]);
                    float2 f23 = __half22float2(src[1]);
                    val = make_float4(f01.x, f01.y, f23.x, f23.y);
                } else {
                    val = *reinterpret_cast<const float4*>(
                        X + (size_t)gr * K + k0 + cp * 4);
                }
            }
            if (TANH) {
                val.x = tanhf(val.x); val.y = tanhf(val.y);
                val.z = tanhf(val.z); val.w = tanhf(val.w);
            }
            sXT[cp * 4 + 0][row] = val.x;
            sXT[cp * 4 + 1][row] = val.y;
            sXT[cp * 4 + 2][row] = val.z;
            sXT[cp * 4 + 3][row] = val.w;
        }
        __syncthreads();
#pragma unroll
        for (int k = 0; k < KC; k++) {
            float xr[TM], wr[TN];
#pragma unroll
            for (int i = 0; i < TM; i++) xr[i] = sXT[k][ty + 16 * i];
#pragma unroll
            for (int j = 0; j < TN; j++) wr[j] = sW[(k0 + k) * FOUT + tx + 16 * j];
#pragma unroll
            for (int i = 0; i < TM; i++)
#pragma unroll
                for (int j = 0; j < TN; j++)
                    acc[i][j] += xr[i] * wr[j];
        }
    }
#pragma unroll
    for (int i = 0; i < TM; i++) {
        int gr = row0 + ty + 16 * i;
        if (gr < N) {
#pragma unroll
            for (int j = 0; j < TN; j++)
                out[(size_t)gr * FOUT + tx + 16 * j] = __float2half_rn(acc[i][j]);
        }
    }
}

__global__ void k_gemm1(const float* __restrict__ X, const float* __restrict__ W, int N) {
    gemm_body<128, 64, 4, false, float>(X, W, reinterpret_cast<__half*>(g_xw1h), N);
}
__global__ void k_gemm2(const float* __restrict__ W, int N) {
    gemm_body<64, 32, 2, false, __half>(
        reinterpret_cast<const __half*>(g_h1h), W, g_xw2h, N);
}
__global__ void k_gemm3(const float* __restrict__ emb, const float* __restrict__ W, int N) {
    gemm_body<32, 16, 1, true, float>(emb, W, g_xw3h, N);
}

// ---------------- layer 1 agg: half2 gathers, 8x unroll, fp16 h1 out --------
__global__ void k_agg1(const float* __restrict__ b1, int N) {
    int node = (blockIdx.x * blockDim.x + threadIdx.x) >> 5;
    if (node >= N) return;
    int lane = threadIdx.x & 31;
    int beg = g_ptr[node], end = g_ptr[node + 1];
    float a0 = 0.0f, a1 = 0.0f;
    int p = beg;
    for (; p + 8 <= end; p += 8) {
        int2 e0 = g_edge[p],     e1 = g_edge[p + 1];
        int2 e2 = g_edge[p + 2], e3 = g_edge[p + 3];
        int2 e4 = g_edge[p + 4], e5 = g_edge[p + 5];
        int2 e6 = g_edge[p + 6], e7 = g_edge[p + 7];
        float2 v0 = __half22float2(g_xw1h[(size_t)e0.x * 32 + lane]);
        float2 v1 = __half22float2(g_xw1h[(size_t)e1.x * 32 + lane]);
        float2 v2 = __half22float2(g_xw1h[(size_t)e2.x * 32 + lane]);
        float2 v3 = __half22float2(g_xw1h[(size_t)e3.x * 32 + lane]);
        float2 v4 = __half22float2(g_xw1h[(size_t)e4.x * 32 + lane]);
        float2 v5 = __half22float2(g_xw1h[(size_t)e5.x * 32 + lane]);
        float2 v6 = __half22float2(g_xw1h[(size_t)e6.x * 32 + lane]);
        float2 v7 = __half22float2(g_xw1h[(size_t)e7.x * 32 + lane]);
        float n0 = __int_as_float(e0.y), n1 = __int_as_float(e1.y);
        float n2 = __int_as_float(e2.y), n3 = __int_as_float(e3.y);
        float n4 = __int_as_float(e4.y), n5 = __int_as_float(e5.y);
        float n6 = __int_as_float(e6.y), n7 = __int_as_float(e7.y);
        a0 += n0 * v0.x; a1 += n0 * v0.y;
        a0 += n1 * v1.x; a1 += n1 * v1.y;
        a0 += n2 * v2.x; a1 += n2 * v2.y;
        a0 += n3 * v3.x; a1 += n3 * v3.y;
        a0 += n4 * v4.x; a1 += n4 * v4.y;
        a0 += n5 * v5.x; a1 += n5 * v5.y;
        a0 += n6 * v6.x; a1 += n6 * v6.y;
        a0 += n7 * v7.x; a1 += n7 * v7.y;
    }
    for (; p < end; p++) {
        int2 e = g_edge[p];
        float2 v = __half22float2(g_xw1h[(size_t)e.x * 32 + lane]);
        float nm = __int_as_float(e.y);
        a0 += nm * v.x;
        a1 += nm * v.y;
    }
    float di = g_dinv[node];
    float d2 = di * di;
    float2 sv = __half22float2(g_xw1h[(size_t)node * 32 + lane]);
    float2 bb = reinterpret_cast<const float2*>(b1)[lane];
    float h0 = tanhf(a0 + d2 * sv.x + bb.x);
    float h1 = tanhf(a1 + d2 * sv.y + bb.y);
    g_h1h[(size_t)node * 32 + lane] = __floats2half2_rn(h0, h1);
}

// ---------------- layer 2 agg: half gathers, 8x unroll, writes emb ----------
__global__ void k_agg2(const float* __restrict__ b2, float* __restrict__ emb, int N) {
    int node = (blockIdx.x * blockDim.x + threadIdx.x) >> 5;
    if (node >= N) return;
    int lane = threadIdx.x & 31;
    int beg = g_ptr[node], end = g_ptr[node + 1];
    float a = 0.0f;
    int p = beg;
    for (; p + 8 <= end; p += 8) {
        int2 e0 = g_edge[p],     e1 = g_edge[p + 1];
        int2 e2 = g_edge[p + 2], e3 = g_edge[p + 3];
        int2 e4 = g_edge[p + 4], e5 = g_edge[p + 5];
        int2 e6 = g_edge[p + 6], e7 = g_edge[p + 7];
        float v0 = __half2float(g_xw2h[(size_t)e0.x * 32 + lane]);
        float v1 = __half2float(g_xw2h[(size_t)e1.x * 32 + lane]);
        float v2 = __half2float(g_xw2h[(size_t)e2.x * 32 + lane]);
        float v3 = __half2float(g_xw2h[(size_t)e3.x * 32 + lane]);
        float v4 = __half2float(g_xw2h[(size_t)e4.x * 32 + lane]);
        float v5 = __half2float(g_xw2h[(size_t)e5.x * 32 + lane]);
        float v6 = __half2float(g_xw2h[(size_t)e6.x * 32 + lane]);
        float v7 = __half2float(g_xw2h[(size_t)e7.x * 32 + lane]);
        a += __int_as_float(e0.y) * v0;
        a += __int_as_float(e1.y) * v1;
        a += __int_as_float(e2.y) * v2;
        a += __int_as_float(e3.y) * v3;
        a += __int_as_float(e4.y) * v4;
        a += __int_as_float(e5.y) * v5;
        a += __int_as_float(e6.y) * v6;
        a += __int_as_float(e7.y) * v7;
    }
    for (; p < end; p++) {
        int2 e = g_edge[p];
        a += __int_as_float(e.y) * __half2float(g_xw2h[(size_t)e.x * 32 + lane]);
    }
    float di = g_dinv[node];
    float val = a + di * di * __half2float(g_xw2h[(size_t)node * 32 + lane]) + b2[lane];
    emb[(size_t)node * 32 + lane] = val;
}

// ---------------- layer 3 agg: half gathers, half-warp edge split -----------
__global__ void k_agg3(const float* __restrict__ b3, float* __restrict__ logits, int N) {
    int node = (blockIdx.x * blockDim.x + threadIdx.x) >> 5;
    if (node >= N) return;
    int lane = threadIdx.x & 31;
    int sub = lane >> 4;
    int f = lane & 15;
    int beg = g_ptr[node], end = g_ptr[node + 1];
    float a = 0.0f;
    int p = beg + sub;
    for (; p + 8 <= end; p += 8) {
        int2 e0 = g_edge[p],     e1 = g_edge[p + 2];
        int2 e2 = g_edge[p + 4], e3 = g_edge[p + 6];
        float v0 = __half2float(g_xw3h[(size_t)e0.x * 16 + f]);
        float v1 = __half2float(g_xw3h[(size_t)e1.x * 16 + f]);
        float v2 = __half2float(g_xw3h[(size_t)e2.x * 16 + f]);
        float v3 = __half2float(g_xw3h[(size_t)e3.x * 16 + f]);
        a += __int_as_float(e0.y) * v0;
        a += __int_as_float(e1.y) * v1;
        a += __int_as_float(e2.y) * v2;
        a += __int_as_float(e3.y) * v3;
    }
    for (; p < end; p += 2) {
        int2 e = g_edge[p];
        a += __int_as_float(e.y) * __half2float(g_xw3h[(size_t)e.x * 16 + f]);
    }
    a += __shfl_xor_sync(0xffffffffu, a, 16);
    if (sub == 0) {
        float di = g_dinv[node];
        logits[(size_t)node * 16 + f] =
            a + di * di * __half2float(g_xw3h[(size_t)node * 16 + f]) + b3[f];
    }
}

// ---------------- launch: fork-join (CSR build || GEMM1) --------------------
extern "C" void kernel_launch(void* const* d_in, const int* in_sizes, int n_in,
                              void* d_out, int out_size) {
    const float* x  = (const float*)d_in[0];
    const int*   ei = (const int*)d_in[1];
    const float* ew = (const float*)d_in[2];
    const float* W1 = (const float*)d_in[3];
    const float* b1 = (const float*)d_in[4];
    const float* W2 = (const float*)d_in[5];
    const float* b2 = (const float*)d_in[6];
    const float* W3 = (const float*)d_in[7];
    const float* b3 = (const float*)d_in[8];

    const int N = in_sizes[0] / 128;
    const int E = in_sizes[2];

    float* logits = (float*)d_out;                    // [N,16]
    float* emb    = (float*)d_out + (size_t)N * 16;   // [N,32]

    const int T = 256;
    auto cdiv = [](long long a, long long b) { return (int)((a + b - 1) / b); };
    const int warpGrid = cdiv((long long)N * 32, T);
    const int nb = cdiv(N, SCAN_T);

    static cudaStream_t s_aux = nullptr;
    static cudaEvent_t ev_fork = nullptr, ev_join = nullptr;
    if (s_aux == nullptr) {
        cudaStreamCreate(&s_aux);
        cudaEventCreateWithFlags(&ev_fork, cudaEventDisableTiming);
        cudaEventCreateWithFlags(&ev_join, cudaEventDisableTiming);
    }

    // ---- fork: CSR build on aux stream (5 kernels, no init pass) ----
    cudaEventRecord(ev_fork, 0);
    cudaStreamWaitEvent(s_aux, ev_fork, 0);
    k_cnt  <<<cdiv(E, T), T, 0, s_aux>>>(ei, ew, E, N);
    k_scan1<<<nb, SCAN_T, 0, s_aux>>>(N);
    k_scan2<<<1, 128,    0, s_aux>>>(nb);
    k_scan3<<<nb, SCAN_T, 0, s_aux>>>(N, E);
    k_fill <<<cdiv(E, T), T, 0, s_aux>>>(ei, ew, E, N);
    cudaEventRecord(ev_join, s_aux);

    // ---- concurrent on main stream: layer-1 GEMM ----
    k_gemm1<<<cdiv(N, 128), T>>>(x, W1, N);

    // ---- join, then the dependent chain ----
    cudaStreamWaitEvent(0, ev_join, 0);
    k_agg1 <<<warpGrid, T>>>(b1, N);
    k_gemm2<<<cdiv(N, 128), T>>>(W2, N);
    k_agg2 <<<warpGrid, T>>>(b2, emb, N);
    k_gemm3<<<cdiv(N, 128), T>>>(emb, W3, N);
    k_agg3 <<<warpGrid, T>>>(b3, logits, N);
}

// round 17
// speedup vs baseline: 1.1116x; 1.1116x over previous
#include <cuda_runtime.h>
#include <cuda_fp16.h>
#include <cstdint>

#define NMAX 100000
#define EMAX 1600000
#define SCAN_T 1024
#define MAXBLK 128

// ---------------- scratch (device globals, device-side references only) -----
__device__ int    g_is64;
__device__ float  g_deg  [NMAX];
__device__ float  g_dinv [NMAX];
__device__ int    g_cnt  [NMAX];
__device__ int    g_part [NMAX];
__device__ int    g_bsum [MAXBLK];
__device__ int    g_ptr  [NMAX + 1];
__device__ int    g_cur  [NMAX];
__device__ int2   g_edge [EMAX];       // CSR slot: (src row, norm bits)
__device__ __half2 g_xw1h[NMAX * 32];  // fp16 gather table, layer 1 (64 feat)
__device__ float  g_h1  [NMAX * 64];   // fp32 (streamed, not gathered)
__device__ __half g_xw2h[NMAX * 32];   // fp16 gather table, layer 2
__device__ __half g_xw3h[NMAX * 16];   // fp16 gather table, layer 3

// ---------------- init + dtype probe ----------------------------------------
__global__ void k_init(const int* __restrict__ ei32, int n) {
    int i = blockIdx.x * blockDim.x + threadIdx.x;
    if (i < n) { g_cnt[i] = 0; g_deg[i] = 1.0f; }   // 1 = self-loop weight
    if (i == 0) {
        int z = 0;
#pragma unroll
        for (int j = 1; j < 16; j += 2) z |= ei32[j];
        g_is64 = (z == 0) ? 1 : 0;
    }
}

__device__ __forceinline__ int load_idx(const int* ei, int pos) {
    return g_is64 ? ei[2 * pos] : ei[pos];
}

__global__ void k_cnt(const int* __restrict__ ei, const float* __restrict__ ew,
                      int E, int N) {
    int e = blockIdx.x * blockDim.x + threadIdx.x;
    if (e < E) {
        int c = load_idx(ei, E + e);
        if ((unsigned)c >= (unsigned)N) c = 0;
        atomicAdd(&g_cnt[c], 1);
        atomicAdd(&g_deg[c], ew[e]);
    }
}

// ---------------- 3-phase parallel exclusive scan of g_cnt ------------------
__global__ void k_scan1(int n) {
    __shared__ int swarp[32];
    int i = blockIdx.x * SCAN_T + threadIdx.x;
    int lane = threadIdx.x & 31;
    int warp = threadIdx.x >> 5;
    int v = (i < n) ? g_cnt[i] : 0;
    int x = v;
#pragma unroll
    for (int o = 1; o < 32; o <<= 1) {
        int y = __shfl_up_sync(0xffffffffu, x, o);
        if (lane >= o) x += y;
    }
    if (lane == 31) swarp[warp] = x;
    __syncthreads();
    if (warp == 0) {
        int w = swarp[lane];
#pragma unroll
        for (int o = 1; o < 32; o <<= 1) {
            int y = __shfl_up_sync(0xffffffffu, w, o);
            if (lane >= o) w += y;
        }
        swarp[lane] = w;
    }
    __syncthreads();
    int warpoff = (warp > 0) ? swarp[warp - 1] : 0;
    if (i < n) g_part[i] = warpoff + x - v;
    if (threadIdx.x == SCAN_T - 1) g_bsum[blockIdx.x] = warpoff + x;
}

__global__ void k_scan2(int nb) {
    __shared__ int s[128];
    int t = threadIdx.x;
    int v = (t < nb) ? g_bsum[t] : 0;
    s[t] = v;
    __syncthreads();
#pragma unroll
    for (int o = 1; o < 128; o <<= 1) {
        int y = (t >= o) ? s[t - o] : 0;
        __syncthreads();
        s[t] += y;
        __syncthreads();
    }
    if (t < nb) g_bsum[t] = s[t] - v;
}

__global__ void k_scan3(int n, int E) {
    int i = blockIdx.x * SCAN_T + threadIdx.x;
    if (i < n) {
        int p = g_part[i] + g_bsum[blockIdx.x];
        g_ptr[i] = p;
        g_cur[i] = p;
        g_dinv[i] = rsqrtf(g_deg[i]);
    }
    if (i == 0) g_ptr[n] = E;
}

__global__ void k_fill(const int* __restrict__ ei, const float* __restrict__ ew,
                       int E, int N) {
    int e = blockIdx.x * blockDim.x + threadIdx.x;
    if (e >= E) return;
    int r = load_idx(ei, e);
    int c = load_idx(ei, E + e);
    if ((unsigned)r >= (unsigned)N) r = 0;
    if ((unsigned)c >= (unsigned)N) c = 0;
    float nm = g_dinv[r] * ew[e] * g_dinv[c];
    int pos = atomicAdd(&g_cur[c], 1);
    g_edge[pos] = make_int2(r, __float_as_int(nm));
}

// ---------------- fp32 SIMT GEMM: BM=128, 8 x TN tile, fp16 output ----------
template<int K, int FOUT, int TN, bool TANH>
__device__ __forceinline__ void gemm_body(const float* __restrict__ X,
                                          const float* __restrict__ W,
                                          __half* __restrict__ out, int N) {
    constexpr int BM = 128;
    constexpr int TM = 8;
    constexpr int KC = 32;
    __shared__ float sW[K * FOUT];
    __shared__ float sXT[KC][BM + 1];

    const int tid = threadIdx.x;
    const int tx  = tid & 15;
    const int ty  = tid >> 4;
    const int row0 = blockIdx.x * BM;

    {
        const float4* W4 = reinterpret_cast<const float4*>(W);
        float4* sW4 = reinterpret_cast<float4*>(sW);
        for (int i = tid; i < K * FOUT / 4; i += 256) sW4[i] = W4[i];
    }

    float acc[TM][TN];
#pragma unroll
    for (int i = 0; i < TM; i++)
#pragma unroll
        for (int j = 0; j < TN; j++) acc[i][j] = 0.0f;

    for (int k0 = 0; k0 < K; k0 += KC) {
        __syncthreads();
#pragma unroll
        for (int t = 0; t < (BM * KC / 4) / 256; t++) {
            int v = tid + 256 * t;
            int row = v >> 3;
            int cp  = v & 7;
            int gr = row0 + row;
            float4 val = make_float4(0.f, 0.f, 0.f, 0.f);
            if (gr < N)
                val = *reinterpret_cast<const float4*>(X + (size_t)gr * K + k0 + cp * 4);
            if (TANH) {
                val.x = tanhf(val.x); val.y = tanhf(val.y);
                val.z = tanhf(val.z); val.w = tanhf(val.w);
            }
            sXT[cp * 4 + 0][row] = val.x;
            sXT[cp * 4 + 1][row] = val.y;
            sXT[cp * 4 + 2][row] = val.z;
            sXT[cp * 4 + 3][row] = val.w;
        }
        __syncthreads();
#pragma unroll
        for (int k = 0; k < KC; k++) {
            float xr[TM], wr[TN];
#pragma unroll
            for (int i = 0; i < TM; i++) xr[i] = sXT[k][ty + 16 * i];
#pragma unroll
            for (int j = 0; j < TN; j++) wr[j] = sW[(k0 + k) * FOUT + tx + 16 * j];
#pragma unroll
            for (int i = 0; i < TM; i++)
#pragma unroll
                for (int j = 0; j < TN; j++)
                    acc[i][j] += xr[i] * wr[j];
        }
    }
#pragma unroll
    for (int i = 0; i < TM; i++) {
        int gr = row0 + ty + 16 * i;
        if (gr < N) {
#pragma unroll
            for (int j = 0; j < TN; j++)
                out[(size_t)gr * FOUT + tx + 16 * j] = __float2half_rn(acc[i][j]);
        }
    }
}

__global__ void k_gemm1(const float* __restrict__ X, const float* __restrict__ W, int N) {
    gemm_body<128, 64, 4, false>(X, W, reinterpret_cast<__half*>(g_xw1h), N);
}
__global__ void k_gemm2(const float* __restrict__ W, int N) {
    gemm_body<64, 32, 2, false>(g_h1, W, g_xw2h, N);
}
__global__ void k_gemm3(const float* __restrict__ emb, const float* __restrict__ W, int N) {
    gemm_body<32, 16, 1, true>(emb, W, g_xw3h, N);
}

// ---------------- layer 1 agg: half2 gathers, 8x unroll ---------------------
__global__ void k_agg1(const float* __restrict__ b1, int N) {
    int node = (blockIdx.x * blockDim.x + threadIdx.x) >> 5;
    if (node >= N) return;
    int lane = threadIdx.x & 31;
    int beg = g_ptr[node], end = g_ptr[node + 1];
    float a0 = 0.0f, a1 = 0.0f;
    int p = beg;
    for (; p + 8 <= end; p += 8) {
        int2 e0 = g_edge[p],     e1 = g_edge[p + 1];
        int2 e2 = g_edge[p + 2], e3 = g_edge[p + 3];
        int2 e4 = g_edge[p + 4], e5 = g_edge[p + 5];
        int2 e6 = g_edge[p + 6], e7 = g_edge[p + 7];
        float2 v0 = __half22float2(g_xw1h[(size_t)e0.x * 32 + lane]);
        float2 v1 = __half22float2(g_xw1h[(size_t)e1.x * 32 + lane]);
        float2 v2 = __half22float2(g_xw1h[(size_t)e2.x * 32 + lane]);
        float2 v3 = __half22float2(g_xw1h[(size_t)e3.x * 32 + lane]);
        float2 v4 = __half22float2(g_xw1h[(size_t)e4.x * 32 + lane]);
        float2 v5 = __half22float2(g_xw1h[(size_t)e5.x * 32 + lane]);
        float2 v6 = __half22float2(g_xw1h[(size_t)e6.x * 32 + lane]);
        float2 v7 = __half22float2(g_xw1h[(size_t)e7.x * 32 + lane]);
        float n0 = __int_as_float(e0.y), n1 = __int_as_float(e1.y);
        float n2 = __int_as_float(e2.y), n3 = __int_as_float(e3.y);
        float n4 = __int_as_float(e4.y), n5 = __int_as_float(e5.y);
        float n6 = __int_as_float(e6.y), n7 = __int_as_float(e7.y);
        a0 += n0 * v0.x; a1 += n0 * v0.y;
        a0 += n1 * v1.x; a1 += n1 * v1.y;
        a0 += n2 * v2.x; a1 += n2 * v2.y;
        a0 += n3 * v3.x; a1 += n3 * v3.y;
        a0 += n4 * v4.x; a1 += n4 * v4.y;
        a0 += n5 * v5.x; a1 += n5 * v5.y;
        a0 += n6 * v6.x; a1 += n6 * v6.y;
        a0 += n7 * v7.x; a1 += n7 * v7.y;
    }
    for (; p < end; p++) {
        int2 e = g_edge[p];
        float2 v = __half22float2(g_xw1h[(size_t)e.x * 32 + lane]);
        float nm = __int_as_float(e.y);
        a0 += nm * v.x;
        a1 += nm * v.y;
    }
    float di = g_dinv[node];
    float d2 = di * di;
    float2 sv = __half22float2(g_xw1h[(size_t)node * 32 + lane]);
    float2 bb = reinterpret_cast<const float2*>(b1)[lane];
    float h0 = tanhf(a0 + d2 * sv.x + bb.x);
    float h1 = tanhf(a1 + d2 * sv.y + bb.y);
    reinterpret_cast<float2*>(g_h1)[(size_t)node * 32 + lane] = make_float2(h0, h1);
}

// ---------------- layer 2 agg: half gathers, 8x unroll, writes emb ----------
__global__ void k_agg2(const float* __restrict__ b2, float* __restrict__ emb, int N) {
    int node = (blockIdx.x * blockDim.x + threadIdx.x) >> 5;
    if (node >= N) return;
    int lane = threadIdx.x & 31;
    int beg = g_ptr[node], end = g_ptr[node + 1];
    float a = 0.0f;
    int p = beg;
    for (; p + 8 <= end; p += 8) {
        int2 e0 = g_edge[p],     e1 = g_edge[p + 1];
        int2 e2 = g_edge[p + 2], e3 = g_edge[p + 3];
        int2 e4 = g_edge[p + 4], e5 = g_edge[p + 5];
        int2 e6 = g_edge[p + 6], e7 = g_edge[p + 7];
        float v0 = __half2float(g_xw2h[(size_t)e0.x * 32 + lane]);
        float v1 = __half2float(g_xw2h[(size_t)e1.x * 32 + lane]);
        float v2 = __half2float(g_xw2h[(size_t)e2.x * 32 + lane]);
        float v3 = __half2float(g_xw2h[(size_t)e3.x * 32 + lane]);
        float v4 = __half2float(g_xw2h[(size_t)e4.x * 32 + lane]);
        float v5 = __half2float(g_xw2h[(size_t)e5.x * 32 + lane]);
        float v6 = __half2float(g_xw2h[(size_t)e6.x * 32 + lane]);
        float v7 = __half2float(g_xw2h[(size_t)e7.x * 32 + lane]);
        a += __int_as_float(e0.y) * v0;
        a += __int_as_float(e1.y) * v1;
        a += __int_as_float(e2.y) * v2;
        a += __int_as_float(e3.y) * v3;
        a += __int_as_float(e4.y) * v4;
        a += __int_as_float(e5.y) * v5;
        a += __int_as_float(e6.y) * v6;
        a += __int_as_float(e7.y) * v7;
    }
    for (; p < end; p++) {
        int2 e = g_edge[p];
        a += __int_as_float(e.y) * __half2float(g_xw2h[(size_t)e.x * 32 + lane]);
    }
    float di = g_dinv[node];
    float val = a + di * di * __half2float(g_xw2h[(size_t)node * 32 + lane]) + b2[lane];
    emb[(size_t)node * 32 + lane] = val;
}

// ---------------- layer 3 agg: half gathers, half-warp edge split -----------
__global__ void k_agg3(const float* __restrict__ b3, float* __restrict__ logits, int N) {
    int node = (blockIdx.x * blockDim.x + threadIdx.x) >> 5;
    if (node >= N) return;
    int lane = threadIdx.x & 31;
    int sub = lane >> 4;
    int f = lane & 15;
    int beg = g_ptr[node], end = g_ptr[node + 1];
    float a = 0.0f;
    int p = beg + sub;
    for (; p + 8 <= end; p += 8) {
        int2 e0 = g_edge[p],     e1 = g_edge[p + 2];
        int2 e2 = g_edge[p + 4], e3 = g_edge[p + 6];
        float v0 = __half2float(g_xw3h[(size_t)e0.x * 16 + f]);
        float v1 = __half2float(g_xw3h[(size_t)e1.x * 16 + f]);
        float v2 = __half2float(g_xw3h[(size_t)e2.x * 16 + f]);
        float v3 = __half2float(g_xw3h[(size_t)e3.x * 16 + f]);
        a += __int_as_float(e0.y) * v0;
        a += __int_as_float(e1.y) * v1;
        a += __int_as_float(e2.y) * v2;
        a += __int_as_float(e3.y) * v3;
    }
    for (; p < end; p += 2) {
        int2 e = g_edge[p];
        a += __int_as_float(e.y) * __half2float(g_xw3h[(size_t)e.x * 16 + f]);
    }
    a += __shfl_xor_sync(0xffffffffu, a, 16);
    if (sub == 0) {
        float di = g_dinv[node];
        logits[(size_t)node * 16 + f] =
            a + di * di * __half2float(g_xw3h[(size_t)node * 16 + f]) + b3[f];
    }
}

// ---------------- launch: fork-join (CSR build || GEMM1) --------------------
extern "C" void kernel_launch(void* const* d_in, const int* in_sizes, int n_in,
                              void* d_out, int out_size) {
    const float* x  = (const float*)d_in[0];
    const int*   ei = (const int*)d_in[1];
    const float* ew = (const float*)d_in[2];
    const float* W1 = (const float*)d_in[3];
    const float* b1 = (const float*)d_in[4];
    const float* W2 = (const float*)d_in[5];
    const float* b2 = (const float*)d_in[6];
    const float* W3 = (const float*)d_in[7];
    const float* b3 = (const float*)d_in[8];

    const int N = in_sizes[0] / 128;
    const int E = in_sizes[2];

    float* logits = (float*)d_out;                    // [N,16]
    float* emb    = (float*)d_out + (size_t)N * 16;   // [N,32]

    const int T = 256;
    auto cdiv = [](long long a, long long b) { return (int)((a + b - 1) / b); };
    const int warpGrid = cdiv((long long)N * 32, T);
    const int nb = cdiv(N, SCAN_T);

    static cudaStream_t s_aux = nullptr;
    static cudaEvent_t ev_fork = nullptr, ev_join = nullptr;
    if (s_aux == nullptr) {
        cudaStreamCreate(&s_aux);
        cudaEventCreateWithFlags(&ev_fork, cudaEventDisableTiming);
        cudaEventCreateWithFlags(&ev_join, cudaEventDisableTiming);
    }

    // ---- fork: CSR build on aux stream ----
    cudaEventRecord(ev_fork, 0);
    cudaStreamWaitEvent(s_aux, ev_fork, 0);
    k_init <<<cdiv(N, T), T, 0, s_aux>>>(ei, N);
    k_cnt  <<<cdiv(E, T), T, 0, s_aux>>>(ei, ew, E, N);
    k_scan1<<<nb, SCAN_T, 0, s_aux>>>(N);
    k_scan2<<<1, 128,    0, s_aux>>>(nb);
    k_scan3<<<nb, SCAN_T, 0, s_aux>>>(N, E);
    k_fill <<<cdiv(E, T), T, 0, s_aux>>>(ei, ew, E, N);
    cudaEventRecord(ev_join, s_aux);

    // ---- concurrent on main stream: layer-1 GEMM ----
    k_gemm1<<<cdiv(N, 128), T>>>(x, W1, N);

    // ---- join, then the dependent chain ----
    cudaStreamWaitEvent(0, ev_join, 0);
    k_agg1 <<<warpGrid, T>>>(b1, N);
    k_gemm2<<<cdiv(N, 128), T>>>(W2, N);
    k_agg2 <<<warpGrid, T>>>(b2, emb, N);
    k_gemm3<<<cdiv(N, 128), T>>>(emb, W3, N);
    k_agg3 <<<warpGrid, T>>>(b3, logits, N);
}